// round 16
// baseline (speedup 1.0000x reference)
#include <cuda_runtime.h>
#include <math.h>

#define BB 4
#define TT 128
#define HH 1024
#define EE 512
#define AA 512
#define VV 16000
#define SS 512
#define NB 128
#define NT 512
#define DSMEM ((24*1024*2 + 4096 + 2048)*4)
#define SCALE 1073741824.0f
#define INV_SCALE 9.313225746154785e-10f

// ---------------- persistent device state ----------------
__device__ __align__(16) float d_h[2][BB][HH];        // [0] is the decoder h buffer
__device__ __align__(16) float d_av1[BB][AA];
__device__ __align__(16) float d_enc_out[BB][TT][HH];
__device__ __align__(16) float d_P[BB][AA][TT];
__device__ __align__(16) float d_gi[TT][BB][3*HH];
__device__ unsigned long long d_score_i[BB*TT];
__device__ unsigned long long d_best[2][BB];
__device__ unsigned d_gcnt[16*64];   // 16 group arrival counters, 256B apart
__device__ unsigned d_rcnt2;         // root arrival counter
__device__ unsigned d_flag[NB*64];   // one release flag per block, 256B apart

__device__ __forceinline__ float wred(float v){
    #pragma unroll
    for (int o = 16; o; o >>= 1) v += __shfl_down_sync(0xffffffffu, v, o);
    return v;
}
__device__ __forceinline__ float sigm(float x){ return 1.0f / (1.0f + expf(-x)); }

// packed f32x2 fma (Blackwell FFMA2)
__device__ __forceinline__ unsigned long long fma2(double a, double b, unsigned long long c){
    unsigned long long r;
    asm("fma.rn.f32x2 %0, %1, %2, %3;" : "=l"(r)
        : "l"(__double_as_longlong(a)), "l"(__double_as_longlong(b)), "l"(c));
    return r;
}
__device__ __forceinline__ float upk(unsigned long long a){
    return __uint_as_float((unsigned)a) + __uint_as_float((unsigned)(a >> 32));
}
// order-preserving (value, first-index) packing for atomicMax argmax
__device__ __forceinline__ unsigned long long packbest(float v, int idx){
    unsigned b = __float_as_uint(v);
    unsigned e = (b & 0x80000000u) ? ~b : (b | 0x80000000u);
    return ((unsigned long long)e << 32) | (unsigned long long)(0xFFFFFFFFu - (unsigned)idx);
}

// grid barrier: hierarchical arrival (16 groups x 8 + root) + per-block release flags
__device__ __forceinline__ void gbar(int bl, unsigned gen){
    __syncthreads();
    if (threadIdx.x < 32){
        int lane = threadIdx.x;
        unsigned old = 0u, ro = 0u;
        if (lane == 0){
            asm volatile("atom.acq_rel.gpu.add.u32 %0, [%1], 1;"
                         : "=r"(old) : "l"(&d_gcnt[(bl >> 3)*64]) : "memory");
            if (old == 7u)
                asm volatile("atom.acq_rel.gpu.add.u32 %0, [%1], 1;"
                             : "=r"(ro) : "l"(&d_rcnt2) : "memory");
        }
        old = __shfl_sync(0xffffffffu, old, 0);
        ro  = __shfl_sync(0xffffffffu, ro,  0);
        if (old == 7u && ro == 15u){
            if (lane < 16) d_gcnt[lane*64] = 0u;
            else if (lane == 16) d_rcnt2 = 0u;
            __syncwarp();
            asm volatile("fence.acq_rel.gpu;" ::: "memory");
            #pragma unroll
            for (int i = 0; i < 4; i++)
                asm volatile("st.relaxed.gpu.u32 [%0], %1;"
                             :: "l"(&d_flag[(lane*4 + i)*64]), "r"(gen) : "memory");
        }
        if (lane == 0){
            unsigned f;
            do {
                asm volatile("ld.acquire.gpu.u32 %0, [%1];" : "=r"(f) : "l"(&d_flag[bl*64]) : "memory");
            } while (f != gen);
        }
    }
    __syncthreads();
}

__global__ __launch_bounds__(NT, 1) void seq2seq_kernel(
    const int*   __restrict__ inputs,
    const float* __restrict__ enc_emb, const float* __restrict__ enc_Wih,
    const float* __restrict__ enc_Whh, const float* __restrict__ enc_bih,
    const float* __restrict__ enc_bhh,
    const float* __restrict__ dec_emb, const float* __restrict__ dec_Wih,
    const float* __restrict__ dec_Whh, const float* __restrict__ dec_bih,
    const float* __restrict__ dec_bhh,
    const float* __restrict__ W_av,  const float* __restrict__ b_av,
    const float* __restrict__ W_cls, const float* __restrict__ b_cls,
    float* __restrict__ out)
{
    extern __shared__ __align__(16) float dyn[];
    float* sWih  = dyn;                  // 24x1024 decoder ih rows ([emb 512 | av 512])
    float* sWhh  = dyn + 24*HH;          // 24x1024 (enc rows during encoder, then dec hh rows)
    float* sm_hst = dyn + 48*HH;         // BB*HH staged h (16 KB)
    float* sm_avv = dyn + 48*HH + BB*HH; // BB*AA staged av (8 KB)

    __shared__ float sm_lg[BB*125];
    __shared__ float sm_ge[24*BB];
    __shared__ float sm_phh[24*BB];      // Whh.h_s + bhh   (written in B(s), used in A(s+1))
    __shared__ float sm_pia[24*BB];      // Wih_av.av_s      (written in C(s), used in A(s+1))
    __shared__ float sm_hloc[8*BB];
    __shared__ float sm_bv[16*BB];
    __shared__ int   sm_bi[16*BB];
    __shared__ int   sm_maski[BB*TT];
    __shared__ float sm_bcls[125];
    __shared__ float sm_bih[24];
    __shared__ float sm_bhh[24];
    __shared__ float sm_bav[4];

    const int tid  = threadIdx.x;
    const int bl   = blockIdx.x;
    const int w    = tid >> 5;
    const int lane = tid & 31;
    const int j0   = bl * 8;
    const int base_v = bl * 125;
    unsigned bgen = 0;

    if (tid == 0) d_flag[bl*64] = 0u;
    if (bl == 0 && tid < 8) ((unsigned long long*)d_best)[tid] = 0ull;

    // ---- zero recurrent state (replay determinism) ----
    for (int i = bl*NT + tid; i < 2*BB*HH + BB*AA; i += NB*NT){
        if (i < 2*BB*HH) (&d_h[0][0][0])[i] = 0.f;
        else             (&d_av1[0][0])[i - 2*BB*HH] = 0.f;
    }

    // ---- load this block's 24 enc_Whh rows to SMEM ----
    for (int i = tid; i < 24*HH; i += NT){
        int d = i >> 10, k = i & 1023;
        int jl = d/3, g = d%3;
        sWhh[i] = enc_Whh[(size_t)(g*HH + j0 + jl)*HH + k];
    }

    // ---- setup A: encoder input-gate preactivations ----
    {
        int r0 = bl * 24;
        if (w < 12){
            int row0 = r0 + 2*w, row1 = row0 + 1;
            float w0[16], w1[16];
            #pragma unroll
            for (int i = 0; i < 16; i++){
                w0[i] = enc_Wih[row0*EE + lane + 32*i];
                w1[i] = enc_Wih[row1*EE + lane + 32*i];
            }
            float b0 = enc_bih[row0], b1 = enc_bih[row1];
            for (int tb = 0; tb < TT*BB; tb++){
                int t = tb >> 2, b = tb & 3;
                int tok = inputs[b*TT + t];
                const float* em = enc_emb + (size_t)tok * EE;
                float a0 = 0.f, a1 = 0.f;
                #pragma unroll
                for (int i = 0; i < 16; i++){
                    float e = em[lane + 32*i];
                    a0 += w0[i]*e; a1 += w1[i]*e;
                }
                a0 = wred(a0); a1 = wred(a1);
                if (lane == 0){
                    d_gi[t][b][row0] = a0 + b0;
                    d_gi[t][b][row1] = a1 + b1;
                }
            }
        }
    }
    gbar(bl, ++bgen);

    // ---- encoder scan (SMEM weights, f32x2) ----
    for (int t = 0; t < TT; t++){
        int cur = t & 1, nxt = cur ^ 1;
        for (int d = w; d < 24; d += 16){
            int jl = d/3, g = d%3;
            int row = g*HH + j0 + jl;
            const double2* Wr = (const double2*)(sWhh + d*HH);
            unsigned long long a2[BB] = {0ull,0ull,0ull,0ull};
            #pragma unroll
            for (int i = 0; i < 8; i++){
                int k4 = lane + 32*i;
                double2 wv = Wr[k4];
                #pragma unroll
                for (int b = 0; b < BB; b++){
                    double2 hv = ((const double2*)d_h[cur][b])[k4];
                    a2[b] = fma2(wv.x, hv.x, a2[b]);
                    a2[b] = fma2(wv.y, hv.y, a2[b]);
                }
            }
            #pragma unroll
            for (int b = 0; b < BB; b++){
                float r = wred(upk(a2[b]));
                if (lane == 0) sm_ge[d*BB + b] = r + enc_bhh[row];
            }
        }
        __syncthreads();
        if (tid < 32){
            int jl = tid >> 2, b = tid & 3, j = j0 + jl;
            float gr = sm_ge[(jl*3+0)*BB+b], gz = sm_ge[(jl*3+1)*BB+b], gn = sm_ge[(jl*3+2)*BB+b];
            float ir = d_gi[t][b][j], iz = d_gi[t][b][j+HH], inn = d_gi[t][b][j+2*HH];
            float r = sigm(ir + gr), z = sigm(iz + gz);
            float n = tanhf(inn + r*gn);
            float hp = d_h[cur][b][j];
            float hn = (1.f - z)*n + z*hp;
            d_h[nxt][b][j]     = hn;
            d_enc_out[b][t][j] = hn;
        }
        gbar(bl, ++bgen);
    }

    // ---- setup P: P[b][a][t] = W_av_left[a] . enc_out[b][t] ----
    {
        int a = bl*4 + (w & 3);
        int q = w >> 2;
        float wa[32];
        #pragma unroll
        for (int i = 0; i < 32; i++) wa[i] = W_av[(size_t)a*2*HH + lane + 32*i];
        for (int tb = q*128; tb < q*128 + 128; tb++){
            int t = tb >> 2, b = tb & 3;
            const float* eo = d_enc_out[b][t];
            float acc = 0.f;
            #pragma unroll
            for (int i = 0; i < 32; i++) acc += wa[i] * eo[lane + 32*i];
            acc = wred(acc);
            if (lane == 0) d_P[b][a][t] = acc;
        }
    }
    if (tid < 4) d_score_i[bl*4 + tid] = 0ull;
    gbar(bl, ++bgen);

    // ---- load decoder weight rows to SMEM + stage caches ----
    for (int i = tid; i < 24*HH; i += NT){
        int d = i >> 10, k = i & 1023;
        int jl = d/3, g = d%3;
        size_t row = (size_t)(g*HH + j0 + jl);
        sWih[i] = dec_Wih[row*(size_t)(EE+AA) + k];
        sWhh[i] = dec_Whh[row*(size_t)HH + k];
    }
    if (tid < BB*TT) sm_maski[tid] = (inputs[tid] == 0) ? 1 : 0;
    if (tid < 125)  sm_bcls[tid] = b_cls[base_v + tid];
    if (tid < 24){ int jl = tid/3, g = tid%3; sm_bih[tid] = dec_bih[g*HH + j0 + jl];
                   sm_bhh[tid] = dec_bhh[g*HH + j0 + jl]; }
    if (tid < 4)   sm_bav[tid] = b_av[bl*4 + tid];
    for (int i = tid; i < BB*HH/4; i += NT) ((float4*)sm_hst)[i] = ((const float4*)(&d_h[0][0][0]))[i];
    for (int i = tid; i < 24*BB; i += NT) sm_pia[i] = 0.f;   // av_0 = 0
    __syncthreads();
    // step-0 hh pre-dots: sm_phh = Whh . h_enc + bhh
    for (int d = w; d < 24; d += 16){
        const double2* Wr = (const double2*)(sWhh + d*HH);
        unsigned long long a2[BB] = {0ull,0ull,0ull,0ull};
        #pragma unroll
        for (int i = 0; i < 8; i++){
            int k4 = lane + 32*i;
            double2 wv = Wr[k4];
            #pragma unroll
            for (int b = 0; b < BB; b++){
                double2 hv = ((const double2*)(sm_hst + b*HH))[k4];
                a2[b] = fma2(wv.x, hv.x, a2[b]);
                a2[b] = fma2(wv.y, hv.y, a2[b]);
            }
        }
        #pragma unroll
        for (int b = 0; b < BB; b++){
            float v = wred(upk(a2[b]));
            if (lane == 0) sm_phh[d*BB + b] = v + sm_bhh[d];
        }
    }

    // ---- decoder: 512 greedy steps, 3 grid barriers each ----
    const size_t OUT_ATT = (size_t)SS * BB * VV;

    for (int s = 0; s < SS; s++){
        int cur = s & 1, nxt = cur ^ 1;

        // per-warp ids decode from previous step's packed argmax
        int myid = 0;
        if (s > 0){
            unsigned long long p = d_best[nxt][lane & 3];
            myid = (int)(0xFFFFFFFFu - (unsigned)(p & 0xFFFFFFFFull));
        }

        // ---- phase A: emb dots only (hh/av parts precomputed) + h update + score partials ----
        for (int d = w; d < 24; d += 16){
            const double2* Wr = (const double2*)(sWih + d*HH);   // emb columns = first 128 double2
            const double2* em[BB];
            #pragma unroll
            for (int b = 0; b < BB; b++)
                em[b] = (const double2*)(dec_emb + (size_t)__shfl_sync(0xffffffffu, myid, b) * EE);
            unsigned long long a2[BB] = {0ull,0ull,0ull,0ull};
            #pragma unroll
            for (int i = 0; i < 4; i++){
                int k4 = lane + 32*i;
                double2 wv = Wr[k4];
                #pragma unroll
                for (int b = 0; b < BB; b++){
                    double2 xv = em[b][k4];
                    a2[b] = fma2(wv.x, xv.x, a2[b]);
                    a2[b] = fma2(wv.y, xv.y, a2[b]);
                }
            }
            #pragma unroll
            for (int b = 0; b < BB; b++){
                float v = wred(upk(a2[b]));
                if (lane == 0) sm_ge[d*BB + b] = v + sm_bih[d];
            }
        }
        __syncthreads();
        if (tid < 32){
            int jl = tid >> 2, b = tid & 3, j = j0 + jl;
            float ir  = sm_ge[(jl*3+0)*BB+b] + sm_pia[(jl*3+0)*BB+b];
            float iz  = sm_ge[(jl*3+1)*BB+b] + sm_pia[(jl*3+1)*BB+b];
            float inn = sm_ge[(jl*3+2)*BB+b] + sm_pia[(jl*3+2)*BB+b];
            float gr  = sm_phh[(jl*3+0)*BB+b];
            float gz  = sm_phh[(jl*3+1)*BB+b];
            float gn  = sm_phh[(jl*3+2)*BB+b];
            float r = sigm(ir + gr), z = sigm(iz + gz);
            float n = tanhf(inn + r*gn);
            float hp = sm_hst[b*HH + j];          // h_{s-1}, staged in previous B (or setup)
            float hn = (1.f - z)*n + z*hp;
            d_h[0][b][j] = hn;
            sm_hloc[jl*4 + b] = hn;
        }
        __syncthreads();
        {   // one (b,t) score partial per thread over this block's 8 h dims
            int t = tid & 127, b = tid >> 7;
            const float4* eo = (const float4*)(&d_enc_out[b][t][j0]);
            float4 e0 = eo[0], e1 = eo[1];
            float p = e0.x*sm_hloc[0*4+b] + e0.y*sm_hloc[1*4+b]
                    + e0.z*sm_hloc[2*4+b] + e0.w*sm_hloc[3*4+b]
                    + e1.x*sm_hloc[4*4+b] + e1.y*sm_hloc[5*4+b]
                    + e1.z*sm_hloc[6*4+b] + e1.w*sm_hloc[7*4+b];
            long long pi = llrintf(p * SCALE);
            atomicAdd(&d_score_i[b*TT + t], (unsigned long long)pi);
        }
        gbar(bl, ++bgen);

        // ---- phase B: stage h_s, warp-local softmax + attn_vec, hh pre-dots for s+1 ----
        {
            for (int i = tid; i < BB*HH/4; i += NT)
                ((float4*)sm_hst)[i] = ((const float4*)(&d_h[0][0][0]))[i];
            if (bl == 0 && tid >= 480 && tid < 484)
                d_best[nxt][tid - 480] = 0ull;   // reset slot for step s+1's phase C
            __syncthreads();

            int b = w & 3, aq = w >> 2, a = bl*4 + aq;
            float x[4]; float m = -1e30f;
            #pragma unroll
            for (int i = 0; i < 4; i++){
                int t = lane + 32*i;
                long long v = (long long)d_score_i[b*TT + t];
                float sc = (float)v * INV_SCALE;
                if (sm_maski[b*TT + t]) sc = -1e30f;
                x[i] = sc; m = fmaxf(m, sc);
            }
            #pragma unroll
            for (int o = 16; o; o >>= 1) m = fmaxf(m, __shfl_xor_sync(0xffffffffu, m, o));
            float sum = 0.f;
            #pragma unroll
            for (int i = 0; i < 4; i++){ x[i] = expf(x[i] - m); sum += x[i]; }
            #pragma unroll
            for (int o = 16; o; o >>= 1) sum += __shfl_xor_sync(0xffffffffu, sum, o);
            float inv = 1.f / sum;
            if (bl < BB && w == bl){
                #pragma unroll
                for (int i = 0; i < 4; i++)
                    out[OUT_ATT + ((size_t)s*BB + bl)*TT + lane + 32*i] = x[i] * inv;
            }
            float acc = 0.f;
            #pragma unroll
            for (int i = 0; i < 4; i++)
                acc += (x[i] * inv) * d_P[b][a][lane + 32*i];
            const double2* Wr = (const double2*)(W_av + (size_t)a*2*HH + HH);
            const double2* hv = (const double2*)(sm_hst + b*HH);
            unsigned long long a2 = 0ull;
            #pragma unroll
            for (int i = 0; i < 8; i++){
                int k4 = lane + 32*i;
                double2 wv = Wr[k4]; double2 h2 = hv[k4];
                a2 = fma2(wv.x, h2.x, a2);
                a2 = fma2(wv.y, h2.y, a2);
            }
            acc += upk(a2);
            acc = wred(acc);
            if (lane == 0) d_av1[b][a] = tanhf(acc + sm_bav[aq]);

            // hh pre-dots for step s+1: sm_phh = Whh . h_s + bhh
            for (int d = w; d < 24; d += 16){
                const double2* Wd = (const double2*)(sWhh + d*HH);
                unsigned long long c2[BB] = {0ull,0ull,0ull,0ull};
                #pragma unroll
                for (int i = 0; i < 8; i++){
                    int k4 = lane + 32*i;
                    double2 wv = Wd[k4];
                    #pragma unroll
                    for (int bb2 = 0; bb2 < BB; bb2++){
                        double2 h2 = ((const double2*)(sm_hst + bb2*HH))[k4];
                        c2[bb2] = fma2(wv.x, h2.x, c2[bb2]);
                        c2[bb2] = fma2(wv.y, h2.y, c2[bb2]);
                    }
                }
                #pragma unroll
                for (int bb2 = 0; bb2 < BB; bb2++){
                    float v = wred(upk(c2[bb2]));
                    if (lane == 0) sm_phh[d*BB + bb2] = v + sm_bhh[d];
                }
            }
        }
        gbar(bl, ++bgen);

        // ---- phase C: stage av, logits (double-buffered W_cls), av pre-dots, argmax ----
        {
            for (int i = tid; i < BB*AA/4; i += NT)
                ((float4*)sm_avv)[i] = ((const float4*)(&d_av1[0][0]))[i];
            if (tid < 4) d_score_i[bl*4 + tid] = 0ull;
            __syncthreads();

            double2 rav[BB][4];
            #pragma unroll
            for (int b = 0; b < BB; b++)
                #pragma unroll
                for (int i = 0; i < 4; i++)
                    rav[b][i] = ((const double2*)(sm_avv + b*AA))[lane + 32*i];

            float bestv[BB] = {-3.4e38f,-3.4e38f,-3.4e38f,-3.4e38f};
            int   besti[BB] = {0,0,0,0};

            double2 wb[4];
            {
                const double2* W = (const double2*)(W_cls + (size_t)(base_v + w) * AA);
                #pragma unroll
                for (int i = 0; i < 4; i++) wb[i] = W[lane + 32*i];
            }
            for (int r = w; r < 125; r += 16){
                double2 wv[4];
                #pragma unroll
                for (int i = 0; i < 4; i++) wv[i] = wb[i];
                int rn = r + 16;
                if (rn < 125){
                    const double2* W2 = (const double2*)(W_cls + (size_t)(base_v + rn) * AA);
                    #pragma unroll
                    for (int i = 0; i < 4; i++) wb[i] = W2[lane + 32*i];
                }
                unsigned long long a2[BB] = {0ull,0ull,0ull,0ull};
                #pragma unroll
                for (int i = 0; i < 4; i++)
                    #pragma unroll
                    for (int b = 0; b < BB; b++){
                        a2[b] = fma2(wv[i].x, rav[b][i].x, a2[b]);
                        a2[b] = fma2(wv[i].y, rav[b][i].y, a2[b]);
                    }
                #pragma unroll
                for (int b = 0; b < BB; b++){
                    float lg = wred(upk(a2[b]));
                    if (lane == 0){
                        lg += sm_bcls[r];
                        sm_lg[b*125 + r] = lg;
                        if (lg > bestv[b]){ bestv[b] = lg; besti[b] = base_v + r; }
                    }
                }
            }
            // av pre-dots for step s+1: sm_pia = Wih_av . av_s  (columns 512..1023 of ih rows)
            for (int d = w; d < 24; d += 16){
                const double2* Wd = (const double2*)(sWih + d*HH + EE);
                unsigned long long c2[BB] = {0ull,0ull,0ull,0ull};
                #pragma unroll
                for (int i = 0; i < 4; i++){
                    int k4 = lane + 32*i;
                    double2 wv = Wd[k4];
                    #pragma unroll
                    for (int b = 0; b < BB; b++){
                        double2 av2 = ((const double2*)(sm_avv + b*AA))[k4];
                        c2[b] = fma2(wv.x, av2.x, c2[b]);
                        c2[b] = fma2(wv.y, av2.y, c2[b]);
                    }
                }
                #pragma unroll
                for (int b = 0; b < BB; b++){
                    float v = wred(upk(c2[b]));
                    if (lane == 0) sm_pia[d*BB + b] = v;
                }
            }
            if (lane == 0){
                #pragma unroll
                for (int b = 0; b < BB; b++){ sm_bv[w*BB + b] = bestv[b]; sm_bi[w*BB + b] = besti[b]; }
            }
            __syncthreads();
            for (int i = tid; i < BB*125; i += NT){
                int b = i / 125, r = i % 125;
                out[((size_t)s*BB + b)*VV + base_v + r] = sm_lg[i];
            }
            if (tid < BB){
                int b = tid;
                float best = -3.4e38f; int bi = 0;
                for (int w2 = 0; w2 < 16; w2++){
                    float v = sm_bv[w2*BB + b]; int i2 = sm_bi[w2*BB + b];
                    if (v > best || (v == best && i2 < bi)){ best = v; bi = i2; }
                }
                atomicMax(&d_best[cur][b], packbest(best, bi));
            }
        }
        gbar(bl, ++bgen);
    }
}

extern "C" void kernel_launch(void* const* d_in, const int* in_sizes, int n_in,
                              void* d_out, int out_size)
{
    (void)in_sizes; (void)n_in; (void)out_size;
    cudaFuncSetAttribute(seq2seq_kernel, cudaFuncAttributeMaxDynamicSharedMemorySize, DSMEM);
    seq2seq_kernel<<<NB, NT, DSMEM>>>(
        (const int*)  d_in[0],
        (const float*)d_in[1],  (const float*)d_in[2],  (const float*)d_in[3],
        (const float*)d_in[4],  (const float*)d_in[5],
        (const float*)d_in[6],  (const float*)d_in[7],  (const float*)d_in[8],
        (const float*)d_in[9],  (const float*)d_in[10],
        (const float*)d_in[11], (const float*)d_in[12],
        (const float*)d_in[13], (const float*)d_in[14],
        (float*)d_out);
}